// round 14
// baseline (speedup 1.0000x reference)
#include <cuda_runtime.h>
#include <cuda_fp16.h>
#include <math.h>

#define N_NODES 100000
#define E_EDGES 1600000
#define NB_SCAN 98            // ceil(100000/1024)
// HID = 64, IN = 128, HEADS = 2

// ---------------- scratch (device globals; no allocations allowed) ----------
__device__ float   g_dinv[N_NODES];            // weighted deg -> dinv (in place)
__device__ int     g_cnt[N_NODES];             // in-edge count (no self)
__device__ int     g_off[N_NODES];             // CSR offsets (exclusive scan)
__device__ int     g_cur[N_NODES];             // scatter cursors
__device__ int     g_bsum[128];                // scan block sums
__device__ int2    g_epack[E_EDGES];           // CSR: (src, ew bits) per slot
__device__ __half2 g_hh[N_NODES * 32];         // h (x@gcn_w) packed fp16 pairs
__device__ float   g_acc[N_NODES * 64];        // GCN output (pre-bias/relu)
__device__ __half2 g_h2x[N_NODES * 64];        // h2 packed (head0,head1) per col
__device__ float   g_ss[N_NODES * 2];          // score_src per (node, head)
__device__ float   g_sd[N_NODES * 2];          // score_dst per (node, head)

// ---------------- helpers ----------------------------------------------------
__device__ __forceinline__ float leaky(float a) {
    return a >= 0.f ? a : 0.2f * a;
}

// ---------------- degree / count ----------------------------------------------
__global__ void k_deg_init() {
    int t = blockIdx.x * blockDim.x + threadIdx.x;
    if (t < N_NODES) { g_dinv[t] = 1.0f; g_cnt[t] = 0; }   // self-loop weight 1
}
__global__ void k_deg_edges(const int* __restrict__ dst, const float* __restrict__ ew) {
    int e = blockIdx.x * blockDim.x + threadIdx.x;
    if (e < E_EDGES) {
        int d = dst[e];
        atomicAdd(&g_dinv[d], ew[e]);
        atomicAdd(&g_cnt[d], 1);
    }
}

// ---------------- CSR build: scan + scatter -----------------------------------
__global__ void k_scan1() {        // per-block exclusive scan of g_cnt
    __shared__ int sh[1024];
    int i = blockIdx.x * 1024 + threadIdx.x;
    int v = (i < N_NODES) ? g_cnt[i] : 0;
    sh[threadIdx.x] = v;
    __syncthreads();
#pragma unroll
    for (int off = 1; off < 1024; off <<= 1) {
        int t = (threadIdx.x >= off) ? sh[threadIdx.x - off] : 0;
        __syncthreads();
        sh[threadIdx.x] += t;
        __syncthreads();
    }
    if (i < N_NODES) g_off[i] = sh[threadIdx.x] - v;   // exclusive
    if (threadIdx.x == 1023) g_bsum[blockIdx.x] = sh[1023];
}
__global__ void k_scan2() {        // serial scan of 98 block sums
    if (threadIdx.x == 0) {
        int run = 0;
        for (int b = 0; b < NB_SCAN; b++) { int v = g_bsum[b]; g_bsum[b] = run; run += v; }
    }
}
__global__ void k_scan3() {        // add block base; init cursors; dinv fold
    int i = blockIdx.x * blockDim.x + threadIdx.x;
    if (i < N_NODES) {
        int o = g_off[i] + g_bsum[i >> 10];
        g_off[i] = o;
        g_cur[i] = o;
        g_dinv[i] = rsqrtf(g_dinv[i]);   // deg >= 1 always
    }
}
__global__ void k_scatter(const int* __restrict__ src, const int* __restrict__ dst,
                          const float* __restrict__ ew) {
    int e = blockIdx.x * blockDim.x + threadIdx.x;
    if (e >= E_EDGES) return;
    int d = dst[e];
    int pos = atomicAdd(&g_cur[d], 1);
    g_epack[pos] = make_int2(src[e], __float_as_int(ew[e]));
}

// ---------------- GEMM1: h = x[N,128] @ gcn_w[128,64] -> fp16 packed ---------
// 4 nodes x 8 cols/thread; DOUBLE-BUFFERED X staging: prefetch chunk kc+1 LDGs
// before computing chunk kc -> memory pipe never drains at the sync.
__global__ void k_gemm1(const float* __restrict__ x, const float* __restrict__ W) {
    __shared__ float Ws[128 * 64];       // 32 KB row-major
    __shared__ float Xs[2][128 * 17];    // 2 x 8.7 KB (16-col chunks)
    int tid = threadIdx.x;
    for (int i = tid * 4; i < 128 * 64; i += 256 * 4)
        *(float4*)&Ws[i] = __ldg((const float4*)&W[i]);

    int cg = tid & 7;
    int ng = tid >> 3;                   // 0..31
    int base = blockIdx.x * 128;
    int n0 = base + ng * 4;

    int sn = tid >> 2, sc4 = tid & 3;    // staging coords (rows sn, sn+64)
    int gn0 = base + sn;      if (gn0 >= N_NODES) gn0 = N_NODES - 1;
    int gn1 = base + sn + 64; if (gn1 >= N_NODES) gn1 = N_NODES - 1;
    const float* xr0 = &x[(size_t)gn0 * 128 + sc4 * 4];
    const float* xr1 = &x[(size_t)gn1 * 128 + sc4 * 4];

    float acc[4][8];
#pragma unroll
    for (int i = 0; i < 4; i++)
#pragma unroll
        for (int j = 0; j < 8; j++) acc[i][j] = 0.f;

    // prefetch + stage chunk 0
    float4 p0 = __ldg((const float4*)&xr0[0]);
    float4 p1 = __ldg((const float4*)&xr1[0]);
    {
        float* d0 = &Xs[0][sn * 17 + sc4 * 4];
        float* d1 = &Xs[0][(sn + 64) * 17 + sc4 * 4];
        d0[0] = p0.x; d0[1] = p0.y; d0[2] = p0.z; d0[3] = p0.w;
        d1[0] = p1.x; d1[1] = p1.y; d1[2] = p1.z; d1[3] = p1.w;
    }
    __syncthreads();

#pragma unroll 1
    for (int kc = 0; kc < 8; kc++) {
        int cur = kc & 1;
        if (kc < 7) {
            p0 = __ldg((const float4*)&xr0[(kc + 1) * 16]);
            p1 = __ldg((const float4*)&xr1[(kc + 1) * 16]);
        }
        const float* Xc = Xs[cur];
#pragma unroll 1
        for (int k = 0; k < 16; k++) {
            int kk = kc * 16 + k;
            float4 wa = *(const float4*)&Ws[kk * 64 + cg * 4];
            float4 wb = *(const float4*)&Ws[kk * 64 + 32 + cg * 4];
            float xs0 = Xc[(ng * 4 + 0) * 17 + k];
            float xs1 = Xc[(ng * 4 + 1) * 17 + k];
            float xs2 = Xc[(ng * 4 + 2) * 17 + k];
            float xs3 = Xc[(ng * 4 + 3) * 17 + k];
#pragma unroll
            for (int i = 0; i < 4; i++) {
                float xs = (i == 0) ? xs0 : (i == 1) ? xs1 : (i == 2) ? xs2 : xs3;
                acc[i][0] += xs * wa.x; acc[i][1] += xs * wa.y;
                acc[i][2] += xs * wa.z; acc[i][3] += xs * wa.w;
                acc[i][4] += xs * wb.x; acc[i][5] += xs * wb.y;
                acc[i][6] += xs * wb.z; acc[i][7] += xs * wb.w;
            }
        }
        if (kc < 7) {
            float* d0 = &Xs[cur ^ 1][sn * 17 + sc4 * 4];
            float* d1 = &Xs[cur ^ 1][(sn + 64) * 17 + sc4 * 4];
            d0[0] = p0.x; d0[1] = p0.y; d0[2] = p0.z; d0[3] = p0.w;
            d1[0] = p1.x; d1[1] = p1.y; d1[2] = p1.z; d1[3] = p1.w;
        }
        __syncthreads();
    }
#pragma unroll
    for (int i = 0; i < 4; i++) {
        int n = n0 + i;
        if (n >= N_NODES) break;
        __half2 a01 = __floats2half2_rn(acc[i][0], acc[i][1]);
        __half2 a23 = __floats2half2_rn(acc[i][2], acc[i][3]);
        __half2 b01 = __floats2half2_rn(acc[i][4], acc[i][5]);
        __half2 b23 = __floats2half2_rn(acc[i][6], acc[i][7]);
        uint2 pa, pb;
        pa.x = *(unsigned*)&a01; pa.y = *(unsigned*)&a23;
        pb.x = *(unsigned*)&b01; pb.y = *(unsigned*)&b23;
        *(uint2*)&g_hh[(size_t)n * 32 + 2 * cg]      = pa;   // cols 4cg..4cg+3
        *(uint2*)&g_hh[(size_t)n * 32 + 16 + 2 * cg] = pb;   // cols 32+4cg..
    }
}

// ---------------- GCN aggregation over CSR (no atomics, fp16 gather) ---------
// 16 lanes per node; full 16-edge groups unrolled x4 (MLP), dynamic remainder.
__global__ void k_gcn_agg() {
    int gt = blockIdx.x * blockDim.x + threadIdx.x;
    int n = gt >> 4;
    if (n >= N_NODES) return;
    int t = threadIdx.x & 15;
    unsigned hm = 0xFFFFu << (threadIdx.x & 16);
    float dn = g_dinv[n];
    float c = dn * dn;
    uint2 u = *(const uint2*)&g_hh[(size_t)n * 32 + 2 * t];
    float2 h01 = __half22float2(*(__half2*)&u.x);
    float2 h23 = __half22float2(*(__half2*)&u.y);
    float4 a = make_float4(c * h01.x, c * h01.y, c * h23.x, c * h23.y);   // self
    int beg = g_off[n];
    int cntE = g_cnt[n];
    int end = beg + cntE;
    int fullend = beg + (cntE & ~15);
    for (int j = beg; j < fullend; j += 16) {
        int2 p = __ldg(&g_epack[j + t]);
        int s = p.x;
        float nrm = g_dinv[s] * __int_as_float(p.y) * dn;
#pragma unroll 4
        for (int k = 0; k < 16; k++) {
            int sk   = __shfl_sync(hm, s, k, 16);
            float nk = __shfl_sync(hm, nrm, k, 16);
            uint2 uu = *(const uint2*)&g_hh[(size_t)sk * 32 + 2 * t];
            float2 e01 = __half22float2(*(__half2*)&uu.x);
            float2 e23 = __half22float2(*(__half2*)&uu.y);
            a.x += nk * e01.x; a.y += nk * e01.y;
            a.z += nk * e23.x; a.w += nk * e23.y;
        }
    }
    if (fullend < end) {
        int e = fullend + t;
        int s = 0; float nrm = 0.f;
        if (e < end) {
            int2 p = __ldg(&g_epack[e]);
            s = p.x;
            nrm = g_dinv[s] * __int_as_float(p.y) * dn;
        }
        int cnt = end - fullend;
        for (int k = 0; k < cnt; k++) {
            int sk   = __shfl_sync(hm, s, k, 16);
            float nk = __shfl_sync(hm, nrm, k, 16);
            uint2 uu = *(const uint2*)&g_hh[(size_t)sk * 32 + 2 * t];
            float2 e01 = __half22float2(*(__half2*)&uu.x);
            float2 e23 = __half22float2(*(__half2*)&uu.y);
            a.x += nk * e01.x; a.y += nk * e01.y;
            a.z += nk * e23.x; a.w += nk * e23.y;
        }
    }
    *(float4*)&g_acc[(size_t)n * 64 + t * 4] = a;
}

// ---------------- GEMM2: h2 = relu(g_acc + gcn_b) @ gat_w[64,128] ------------
// 4 nodes x 8 cols/thread; DOUBLE-BUFFERED staging (bias+relu folded);
// packs __half2(h0,h1); scores via shfl.
__global__ void k_gemm2(const float* __restrict__ W, const float* __restrict__ as_,
                        const float* __restrict__ ad_, const float* __restrict__ gb) {
    __shared__ float Ws[64 * 128];      // 32 KB row-major
    __shared__ float Xs[2][64 * 33];    // 2 x 8.4 KB (32-col chunks)
    int tid = threadIdx.x;
    for (int i = tid * 4; i < 64 * 128; i += 256 * 4)
        *(float4*)&Ws[i] = __ldg((const float4*)&W[i]);

    int cg = tid & 15;
    int ng = tid >> 4;                   // 0..15
    int base = blockIdx.x * 64;
    int n0 = base + ng * 4;

    int sn = tid >> 3, sc4 = tid & 7;    // staging coords (rows sn, sn+32)
    int gn0 = base + sn;      if (gn0 >= N_NODES) gn0 = N_NODES - 1;
    int gn1 = base + sn + 32; if (gn1 >= N_NODES) gn1 = N_NODES - 1;

    float acc[4][8];
#pragma unroll
    for (int i = 0; i < 4; i++)
#pragma unroll
        for (int j = 0; j < 8; j++) acc[i][j] = 0.f;

    // prefetch + stage chunk 0 (bias+relu folded)
    float4 p0 = __ldg((const float4*)&g_acc[(size_t)gn0 * 64 + sc4 * 4]);
    float4 p1 = __ldg((const float4*)&g_acc[(size_t)gn1 * 64 + sc4 * 4]);
    float4 bv = __ldg((const float4*)&gb[sc4 * 4]);
    {
        float* d0 = &Xs[0][sn * 33 + sc4 * 4];
        float* d1 = &Xs[0][(sn + 32) * 33 + sc4 * 4];
        d0[0] = fmaxf(p0.x + bv.x, 0.f); d0[1] = fmaxf(p0.y + bv.y, 0.f);
        d0[2] = fmaxf(p0.z + bv.z, 0.f); d0[3] = fmaxf(p0.w + bv.w, 0.f);
        d1[0] = fmaxf(p1.x + bv.x, 0.f); d1[1] = fmaxf(p1.y + bv.y, 0.f);
        d1[2] = fmaxf(p1.z + bv.z, 0.f); d1[3] = fmaxf(p1.w + bv.w, 0.f);
    }
    __syncthreads();

#pragma unroll 1
    for (int kc = 0; kc < 2; kc++) {
        int cur = kc & 1;
        if (kc < 1) {
            p0 = __ldg((const float4*)&g_acc[(size_t)gn0 * 64 + 32 + sc4 * 4]);
            p1 = __ldg((const float4*)&g_acc[(size_t)gn1 * 64 + 32 + sc4 * 4]);
            bv = __ldg((const float4*)&gb[32 + sc4 * 4]);
        }
        const float* Xc = Xs[cur];
#pragma unroll 1
        for (int k = 0; k < 32; k++) {
            int kk = kc * 32 + k;
            float4 wa = *(const float4*)&Ws[kk * 128 + cg * 4];       // head0
            float4 wb = *(const float4*)&Ws[kk * 128 + 64 + cg * 4];  // head1
            float xs0 = Xc[(ng * 4 + 0) * 33 + k];
            float xs1 = Xc[(ng * 4 + 1) * 33 + k];
            float xs2 = Xc[(ng * 4 + 2) * 33 + k];
            float xs3 = Xc[(ng * 4 + 3) * 33 + k];
#pragma unroll
            for (int i = 0; i < 4; i++) {
                float xs = (i == 0) ? xs0 : (i == 1) ? xs1 : (i == 2) ? xs2 : xs3;
                acc[i][0] += xs * wa.x; acc[i][1] += xs * wa.y;
                acc[i][2] += xs * wa.z; acc[i][3] += xs * wa.w;
                acc[i][4] += xs * wb.x; acc[i][5] += xs * wb.y;
                acc[i][6] += xs * wb.z; acc[i][7] += xs * wb.w;
            }
        }
        if (kc < 1) {
            float* d0 = &Xs[cur ^ 1][sn * 33 + sc4 * 4];
            float* d1 = &Xs[cur ^ 1][(sn + 32) * 33 + sc4 * 4];
            d0[0] = fmaxf(p0.x + bv.x, 0.f); d0[1] = fmaxf(p0.y + bv.y, 0.f);
            d0[2] = fmaxf(p0.z + bv.z, 0.f); d0[3] = fmaxf(p0.w + bv.w, 0.f);
            d1[0] = fmaxf(p1.x + bv.x, 0.f); d1[1] = fmaxf(p1.y + bv.y, 0.f);
            d1[2] = fmaxf(p1.z + bv.z, 0.f); d1[3] = fmaxf(p1.w + bv.w, 0.f);
            __syncthreads();
        }
    }
    float4 a0 = __ldg((const float4*)&as_[cg * 4]);
    float4 a1 = __ldg((const float4*)&as_[64 + cg * 4]);
    float4 d0v = __ldg((const float4*)&ad_[cg * 4]);
    float4 d1v = __ldg((const float4*)&ad_[64 + cg * 4]);
#pragma unroll
    for (int i = 0; i < 4; i++) {
        int n = n0 + i;
        bool valid = n < N_NODES;
        if (valid) {
            __half2 q0 = __floats2half2_rn(acc[i][0], acc[i][4]);
            __half2 q1 = __floats2half2_rn(acc[i][1], acc[i][5]);
            __half2 q2 = __floats2half2_rn(acc[i][2], acc[i][6]);
            __half2 q3 = __floats2half2_rn(acc[i][3], acc[i][7]);
            uint4 pk;
            pk.x = *(unsigned*)&q0; pk.y = *(unsigned*)&q1;
            pk.z = *(unsigned*)&q2; pk.w = *(unsigned*)&q3;
            *(uint4*)&g_h2x[(size_t)n * 64 + cg * 4] = pk;
        }
        float ps0 = acc[i][0] * a0.x + acc[i][1] * a0.y + acc[i][2] * a0.z + acc[i][3] * a0.w;
        float pd0 = acc[i][0] * d0v.x + acc[i][1] * d0v.y + acc[i][2] * d0v.z + acc[i][3] * d0v.w;
        float ps1 = acc[i][4] * a1.x + acc[i][5] * a1.y + acc[i][6] * a1.z + acc[i][7] * a1.w;
        float pd1 = acc[i][4] * d1v.x + acc[i][5] * d1v.y + acc[i][6] * d1v.z + acc[i][7] * d1v.w;
#pragma unroll
        for (int off = 1; off < 16; off <<= 1) {
            ps0 += __shfl_xor_sync(0xffffffffu, ps0, off, 16);
            pd0 += __shfl_xor_sync(0xffffffffu, pd0, off, 16);
            ps1 += __shfl_xor_sync(0xffffffffu, ps1, off, 16);
            pd1 += __shfl_xor_sync(0xffffffffu, pd1, off, 16);
        }
        if (cg == 0 && valid) {
            *(float2*)&g_ss[2 * n] = make_float2(ps0, ps1);
            *(float2*)&g_sd[2 * n] = make_float2(pd0, pd1);
        }
    }
}

// ---------------- GAT aggregation over CSR: softmax + mean + bias + relu -----
// Full 16-edge groups unrolled x4 (MLP), dynamic remainder.
__global__ void k_gat_agg(const float* __restrict__ b, float* __restrict__ out) {
    int gt = blockIdx.x * blockDim.x + threadIdx.x;
    int n = gt >> 4;
    if (n >= N_NODES) return;
    int t = threadIdx.x & 15;
    unsigned hm = 0xFFFFu << (threadIdx.x & 16);
    float2 sdv = *(const float2*)&g_sd[2 * n];
    float2 ssn = *(const float2*)&g_ss[2 * n];
    float selfex0 = expf(leaky(ssn.x + sdv.x));
    float selfex1 = expf(leaky(ssn.y + sdv.y));
    uint4 u = *(const uint4*)&g_h2x[(size_t)n * 64 + t * 4];
    float2 f0 = __half22float2(*(__half2*)&u.x);
    float2 f1 = __half22float2(*(__half2*)&u.y);
    float2 f2 = __half22float2(*(__half2*)&u.z);
    float2 f3 = __half22float2(*(__half2*)&u.w);
    float num0[4] = { selfex0 * f0.x, selfex0 * f1.x, selfex0 * f2.x, selfex0 * f3.x };
    float num1[4] = { selfex1 * f0.y, selfex1 * f1.y, selfex1 * f2.y, selfex1 * f3.y };
    float den0 = 0.f, den1 = 0.f;      // edge part; self added post-reduce
    int beg = g_off[n];
    int cntE = g_cnt[n];
    int end = beg + cntE;
    int fullend = beg + (cntE & ~15);
    for (int j = beg; j < fullend; j += 16) {
        int s = __ldg(&g_epack[j + t]).x;
        float2 ssv = *(const float2*)&g_ss[2 * s];
        float ex0 = expf(leaky(ssv.x + sdv.x));
        float ex1 = expf(leaky(ssv.y + sdv.y));
        den0 += ex0; den1 += ex1;
#pragma unroll 4
        for (int k = 0; k < 16; k++) {
            int sk   = __shfl_sync(hm, s, k, 16);
            float c0 = __shfl_sync(hm, ex0, k, 16);
            float c1 = __shfl_sync(hm, ex1, k, 16);
            uint4 uu = *(const uint4*)&g_h2x[(size_t)sk * 64 + t * 4];
            float2 e0 = __half22float2(*(__half2*)&uu.x);
            float2 e1 = __half22float2(*(__half2*)&uu.y);
            float2 e2 = __half22float2(*(__half2*)&uu.z);
            float2 e3 = __half22float2(*(__half2*)&uu.w);
            num0[0] += c0 * e0.x; num1[0] += c1 * e0.y;
            num0[1] += c0 * e1.x; num1[1] += c1 * e1.y;
            num0[2] += c0 * e2.x; num1[2] += c1 * e2.y;
            num0[3] += c0 * e3.x; num1[3] += c1 * e3.y;
        }
    }
    if (fullend < end) {
        int e = fullend + t;
        int s = 0; float ex0 = 0.f, ex1 = 0.f;
        if (e < end) {
            s = __ldg(&g_epack[e]).x;
            float2 ssv = *(const float2*)&g_ss[2 * s];
            ex0 = expf(leaky(ssv.x + sdv.x));
            ex1 = expf(leaky(ssv.y + sdv.y));
        }
        den0 += ex0; den1 += ex1;
        int cnt = end - fullend;
        for (int k = 0; k < cnt; k++) {
            int sk   = __shfl_sync(hm, s, k, 16);
            float c0 = __shfl_sync(hm, ex0, k, 16);
            float c1 = __shfl_sync(hm, ex1, k, 16);
            uint4 uu = *(const uint4*)&g_h2x[(size_t)sk * 64 + t * 4];
            float2 e0 = __half22float2(*(__half2*)&uu.x);
            float2 e1 = __half22float2(*(__half2*)&uu.y);
            float2 e2 = __half22float2(*(__half2*)&uu.z);
            float2 e3 = __half22float2(*(__half2*)&uu.w);
            num0[0] += c0 * e0.x; num1[0] += c1 * e0.y;
            num0[1] += c0 * e1.x; num1[1] += c1 * e1.y;
            num0[2] += c0 * e2.x; num1[2] += c1 * e2.y;
            num0[3] += c0 * e3.x; num1[3] += c1 * e3.y;
        }
    }
#pragma unroll
    for (int off = 1; off < 16; off <<= 1) {
        den0 += __shfl_xor_sync(hm, den0, off, 16);
        den1 += __shfl_xor_sync(hm, den1, off, 16);
    }
    den0 += selfex0;   // every lane computed identical self terms
    den1 += selfex1;
    float r0 = 0.5f / fmaxf(den0, 1e-16f);
    float r1 = 0.5f / fmaxf(den1, 1e-16f);
    float4 bv = __ldg((const float4*)&b[t * 4]);
    *(float4*)&out[(size_t)n * 64 + t * 4] =
        make_float4(fmaxf(num0[0] * r0 + num1[0] * r1 + bv.x, 0.f),
                    fmaxf(num0[1] * r0 + num1[1] * r1 + bv.y, 0.f),
                    fmaxf(num0[2] * r0 + num1[2] * r1 + bv.z, 0.f),
                    fmaxf(num0[3] * r0 + num1[3] * r1 + bv.w, 0.f));
}

// ---------------- launch -----------------------------------------------------
static cudaStream_t g_s2 = 0;
static cudaEvent_t  g_evF = 0, g_evJ = 0;

extern "C" void kernel_launch(void* const* d_in, const int* in_sizes, int n_in,
                              void* d_out, int out_size) {
    const float* x       = (const float*)d_in[0];
    const int*   ei      = (const int*)d_in[1];
    const float* ew      = (const float*)d_in[2];
    const float* gcn_w   = (const float*)d_in[3];
    const float* gcn_b   = (const float*)d_in[4];
    const float* gat_w   = (const float*)d_in[5];
    const float* att_src = (const float*)d_in[6];
    const float* att_dst = (const float*)d_in[7];
    const float* gat_b   = (const float*)d_in[8];
    float* out = (float*)d_out;
    const int* src = ei;
    const int* dst = ei + E_EDGES;

    if (!g_s2) {   // first call is the (uncaptured) correctness run
        cudaStreamCreateWithFlags(&g_s2, cudaStreamNonBlocking);
        cudaEventCreateWithFlags(&g_evF, cudaEventDisableTiming);
        cudaEventCreateWithFlags(&g_evJ, cudaEventDisableTiming);
    }

    const int B = 256;
    // fork: degree + CSR build on stream 2, overlapped with gemm1
    cudaEventRecord(g_evF, 0);
    cudaStreamWaitEvent(g_s2, g_evF, 0);
    k_deg_init<<<(N_NODES + B - 1) / B, B, 0, g_s2>>>();
    k_deg_edges<<<(E_EDGES + B - 1) / B, B, 0, g_s2>>>(dst, ew);
    k_scan1<<<NB_SCAN, 1024, 0, g_s2>>>();
    k_scan2<<<1, 32, 0, g_s2>>>();
    k_scan3<<<(N_NODES + B - 1) / B, B, 0, g_s2>>>();
    k_scatter<<<(E_EDGES + B - 1) / B, B, 0, g_s2>>>(src, dst, ew);
    cudaEventRecord(g_evJ, g_s2);

    // main stream: gemm1 (depends only on x, W)
    k_gemm1<<<(N_NODES + 127) / 128, B>>>(x, gcn_w);

    // join, then the dependent chain
    cudaStreamWaitEvent(0, g_evJ, 0);
    k_gcn_agg<<<(N_NODES * 16 + B - 1) / B, B>>>();
    k_gemm2<<<(N_NODES + 63) / 64, B>>>(gat_w, att_src, att_dst, gcn_b);
    k_gat_agg<<<(N_NODES * 16 + B - 1) / B, B>>>(gat_b, out);
}

// round 15
// speedup vs baseline: 1.0832x; 1.0832x over previous
#include <cuda_runtime.h>
#include <cuda_fp16.h>
#include <math.h>

#define N_NODES 100000
#define E_EDGES 1600000
#define NB_SCAN 98            // ceil(100000/1024)
// HID = 64, IN = 128, HEADS = 2

// ---------------- scratch (device globals; no allocations allowed) ----------
__device__ float   g_dinv[N_NODES];            // weighted deg -> dinv (in place)
__device__ int     g_cnt[N_NODES];             // in-edge count (no self)
__device__ int     g_off[N_NODES];             // CSR offsets (exclusive scan)
__device__ int     g_cur[N_NODES];             // scatter cursors
__device__ int     g_bsum[128];                // scan block sums
__device__ int2    g_epack[E_EDGES];           // CSR: (src, ew bits) per slot
__device__ __half2 g_hh[N_NODES * 32];         // h (x@gcn_w) packed fp16 pairs
__device__ float   g_acc[N_NODES * 64];        // GCN output (pre-bias/relu)
__device__ __half2 g_h2x[N_NODES * 64];        // h2 packed (head0,head1) per col
__device__ float   g_ss[N_NODES * 2];          // score_src per (node, head)
__device__ float   g_sd[N_NODES * 2];          // score_dst per (node, head)

// ---------------- helpers ----------------------------------------------------
__device__ __forceinline__ float leaky(float a) {
    return a >= 0.f ? a : 0.2f * a;
}

// ---------------- degree / count ----------------------------------------------
__global__ void k_deg_init() {
    int t = blockIdx.x * blockDim.x + threadIdx.x;
    if (t < N_NODES) { g_dinv[t] = 1.0f; g_cnt[t] = 0; }   // self-loop weight 1
}
__global__ void k_deg_edges(const int* __restrict__ dst, const float* __restrict__ ew) {
    int e = blockIdx.x * blockDim.x + threadIdx.x;
    if (e < E_EDGES) {
        int d = dst[e];
        atomicAdd(&g_dinv[d], ew[e]);
        atomicAdd(&g_cnt[d], 1);
    }
}

// ---------------- CSR build: scan + scatter -----------------------------------
__global__ void k_scan1() {        // per-block exclusive scan of g_cnt
    __shared__ int sh[1024];
    int i = blockIdx.x * 1024 + threadIdx.x;
    int v = (i < N_NODES) ? g_cnt[i] : 0;
    sh[threadIdx.x] = v;
    __syncthreads();
#pragma unroll
    for (int off = 1; off < 1024; off <<= 1) {
        int t = (threadIdx.x >= off) ? sh[threadIdx.x - off] : 0;
        __syncthreads();
        sh[threadIdx.x] += t;
        __syncthreads();
    }
    if (i < N_NODES) g_off[i] = sh[threadIdx.x] - v;   // exclusive
    if (threadIdx.x == 1023) g_bsum[blockIdx.x] = sh[1023];
}
__global__ void k_scan2() {        // serial scan of 98 block sums
    if (threadIdx.x == 0) {
        int run = 0;
        for (int b = 0; b < NB_SCAN; b++) { int v = g_bsum[b]; g_bsum[b] = run; run += v; }
    }
}
__global__ void k_scan3() {        // add block base; init cursors; dinv fold
    int i = blockIdx.x * blockDim.x + threadIdx.x;
    if (i < N_NODES) {
        int o = g_off[i] + g_bsum[i >> 10];
        g_off[i] = o;
        g_cur[i] = o;
        g_dinv[i] = rsqrtf(g_dinv[i]);   // deg >= 1 always
    }
}
__global__ void k_scatter(const int* __restrict__ src, const int* __restrict__ dst,
                          const float* __restrict__ ew) {
    int e = blockIdx.x * blockDim.x + threadIdx.x;
    if (e >= E_EDGES) return;
    int d = dst[e];
    int pos = atomicAdd(&g_cur[d], 1);
    g_epack[pos] = make_int2(src[e], __float_as_int(ew[e]));
}

// ---------------- GEMM1: h = x[N,128] @ gcn_w[128,64] -> fp16 packed ---------
// 4 nodes x 8 cols/thread; X staged through smem (R9/R13 layout, proven).
__global__ void k_gemm1(const float* __restrict__ x, const float* __restrict__ W) {
    __shared__ float Ws[128 * 64];     // 32 KB row-major
    __shared__ float Xs[128 * 17];     // 8.7 KB (16-col chunks)
    int tid = threadIdx.x;
    for (int i = tid * 4; i < 128 * 64; i += 256 * 4)
        *(float4*)&Ws[i] = __ldg((const float4*)&W[i]);

    int cg = tid & 7;
    int ng = tid >> 3;                 // 0..31
    int n0 = blockIdx.x * 128 + ng * 4;

    float acc[4][8];
#pragma unroll
    for (int i = 0; i < 4; i++)
#pragma unroll
        for (int j = 0; j < 8; j++) acc[i][j] = 0.f;

#pragma unroll 1
    for (int kc = 0; kc < 8; kc++) {
        __syncthreads();
#pragma unroll
        for (int it = 0; it < 2; it++) {
            int g = it * 256 + tid;
            int n = g >> 2, c4 = g & 3;
            int gn = blockIdx.x * 128 + n;
            if (gn >= N_NODES) gn = N_NODES - 1;
            float4 v = __ldg((const float4*)&x[(size_t)gn * 128 + kc * 16 + c4 * 4]);
            float* dp = &Xs[n * 17 + c4 * 4];
            dp[0] = v.x; dp[1] = v.y; dp[2] = v.z; dp[3] = v.w;
        }
        __syncthreads();
#pragma unroll 1
        for (int k = 0; k < 16; k++) {
            int kk = kc * 16 + k;
            float4 wa = *(const float4*)&Ws[kk * 64 + cg * 4];
            float4 wb = *(const float4*)&Ws[kk * 64 + 32 + cg * 4];
            float xs0 = Xs[(ng * 4 + 0) * 17 + k];
            float xs1 = Xs[(ng * 4 + 1) * 17 + k];
            float xs2 = Xs[(ng * 4 + 2) * 17 + k];
            float xs3 = Xs[(ng * 4 + 3) * 17 + k];
#pragma unroll
            for (int i = 0; i < 4; i++) {
                float xs = (i == 0) ? xs0 : (i == 1) ? xs1 : (i == 2) ? xs2 : xs3;
                acc[i][0] += xs * wa.x; acc[i][1] += xs * wa.y;
                acc[i][2] += xs * wa.z; acc[i][3] += xs * wa.w;
                acc[i][4] += xs * wb.x; acc[i][5] += xs * wb.y;
                acc[i][6] += xs * wb.z; acc[i][7] += xs * wb.w;
            }
        }
    }
#pragma unroll
    for (int i = 0; i < 4; i++) {
        int n = n0 + i;
        if (n >= N_NODES) break;
        __half2 a01 = __floats2half2_rn(acc[i][0], acc[i][1]);
        __half2 a23 = __floats2half2_rn(acc[i][2], acc[i][3]);
        __half2 b01 = __floats2half2_rn(acc[i][4], acc[i][5]);
        __half2 b23 = __floats2half2_rn(acc[i][6], acc[i][7]);
        uint2 pa, pb;
        pa.x = *(unsigned*)&a01; pa.y = *(unsigned*)&a23;
        pb.x = *(unsigned*)&b01; pb.y = *(unsigned*)&b23;
        *(uint2*)&g_hh[(size_t)n * 32 + 2 * cg]      = pa;   // cols 4cg..4cg+3
        *(uint2*)&g_hh[(size_t)n * 32 + 16 + 2 * cg] = pb;   // cols 32+4cg..
    }
}

// ---------------- GCN aggregation over CSR (no atomics, fp16 gather) ---------
// 16 lanes per node; edges in groups of 16; half-masked shfl broadcast.
__global__ void k_gcn_agg() {
    int gt = blockIdx.x * blockDim.x + threadIdx.x;
    int n = gt >> 4;
    if (n >= N_NODES) return;
    int t = threadIdx.x & 15;
    unsigned hm = 0xFFFFu << (threadIdx.x & 16);
    float dn = g_dinv[n];
    float c = dn * dn;
    uint2 u = *(const uint2*)&g_hh[(size_t)n * 32 + 2 * t];
    float2 h01 = __half22float2(*(__half2*)&u.x);
    float2 h23 = __half22float2(*(__half2*)&u.y);
    float4 a = make_float4(c * h01.x, c * h01.y, c * h23.x, c * h23.y);   // self
    int beg = g_off[n];
    int end = beg + g_cnt[n];
    for (int j = beg; j < end; j += 16) {
        int e = j + t;
        int s = 0; float nrm = 0.f;
        if (e < end) {
            int2 p = __ldg(&g_epack[e]);
            s = p.x;
            nrm = g_dinv[s] * __int_as_float(p.y) * dn;
        }
        int cnt = min(16, end - j);
        for (int k = 0; k < cnt; k++) {
            int sk   = __shfl_sync(hm, s, k, 16);
            float nk = __shfl_sync(hm, nrm, k, 16);
            uint2 uu = *(const uint2*)&g_hh[(size_t)sk * 32 + 2 * t];
            float2 e01 = __half22float2(*(__half2*)&uu.x);
            float2 e23 = __half22float2(*(__half2*)&uu.y);
            a.x += nk * e01.x; a.y += nk * e01.y;
            a.z += nk * e23.x; a.w += nk * e23.y;
        }
    }
    *(float4*)&g_acc[(size_t)n * 64 + t * 4] = a;
}

// ---------------- GEMM2: h2 = relu(g_acc + gcn_b) @ gat_w[64,128] ------------
// 4 nodes x 8 cols/thread; packs __half2(h0,h1); scores via shfl. (R13 layout.)
__global__ void k_gemm2(const float* __restrict__ W, const float* __restrict__ as_,
                        const float* __restrict__ ad_, const float* __restrict__ gb) {
    __shared__ float Ws[64 * 128];    // 32 KB row-major
    __shared__ float Xs[64 * 33];     // 8.4 KB (32-col chunks)
    int tid = threadIdx.x;
    for (int i = tid * 4; i < 64 * 128; i += 256 * 4)
        *(float4*)&Ws[i] = __ldg((const float4*)&W[i]);

    int cg = tid & 15;
    int ng = tid >> 4;                 // 0..15
    int n0 = blockIdx.x * 64 + ng * 4;

    float acc[4][8];
#pragma unroll
    for (int i = 0; i < 4; i++)
#pragma unroll
        for (int j = 0; j < 8; j++) acc[i][j] = 0.f;

#pragma unroll 1
    for (int kc = 0; kc < 2; kc++) {
        __syncthreads();
#pragma unroll
        for (int it = 0; it < 2; it++) {
            int g = it * 256 + tid;
            int n = g >> 3, c4 = g & 7;
            int gn = blockIdx.x * 64 + n;
            if (gn >= N_NODES) gn = N_NODES - 1;
            float4 raw = __ldg((const float4*)&g_acc[(size_t)gn * 64 + kc * 32 + c4 * 4]);
            float4 bv = __ldg((const float4*)&gb[kc * 32 + c4 * 4]);
            float* dp = &Xs[n * 33 + c4 * 4];
            dp[0] = fmaxf(raw.x + bv.x, 0.f);
            dp[1] = fmaxf(raw.y + bv.y, 0.f);
            dp[2] = fmaxf(raw.z + bv.z, 0.f);
            dp[3] = fmaxf(raw.w + bv.w, 0.f);
        }
        __syncthreads();
#pragma unroll 1
        for (int k = 0; k < 32; k++) {
            int kk = kc * 32 + k;
            float4 wa = *(const float4*)&Ws[kk * 128 + cg * 4];       // head0
            float4 wb = *(const float4*)&Ws[kk * 128 + 64 + cg * 4];  // head1
            float xs0 = Xs[(ng * 4 + 0) * 33 + k];
            float xs1 = Xs[(ng * 4 + 1) * 33 + k];
            float xs2 = Xs[(ng * 4 + 2) * 33 + k];
            float xs3 = Xs[(ng * 4 + 3) * 33 + k];
#pragma unroll
            for (int i = 0; i < 4; i++) {
                float xs = (i == 0) ? xs0 : (i == 1) ? xs1 : (i == 2) ? xs2 : xs3;
                acc[i][0] += xs * wa.x; acc[i][1] += xs * wa.y;
                acc[i][2] += xs * wa.z; acc[i][3] += xs * wa.w;
                acc[i][4] += xs * wb.x; acc[i][5] += xs * wb.y;
                acc[i][6] += xs * wb.z; acc[i][7] += xs * wb.w;
            }
        }
    }
    float4 a0 = __ldg((const float4*)&as_[cg * 4]);
    float4 a1 = __ldg((const float4*)&as_[64 + cg * 4]);
    float4 d0 = __ldg((const float4*)&ad_[cg * 4]);
    float4 d1 = __ldg((const float4*)&ad_[64 + cg * 4]);
#pragma unroll
    for (int i = 0; i < 4; i++) {
        int n = n0 + i;
        bool valid = n < N_NODES;
        if (valid) {
            __half2 p0 = __floats2half2_rn(acc[i][0], acc[i][4]);
            __half2 p1 = __floats2half2_rn(acc[i][1], acc[i][5]);
            __half2 p2 = __floats2half2_rn(acc[i][2], acc[i][6]);
            __half2 p3 = __floats2half2_rn(acc[i][3], acc[i][7]);
            uint4 pk;
            pk.x = *(unsigned*)&p0; pk.y = *(unsigned*)&p1;
            pk.z = *(unsigned*)&p2; pk.w = *(unsigned*)&p3;
            *(uint4*)&g_h2x[(size_t)n * 64 + cg * 4] = pk;
        }
        float ps0 = acc[i][0] * a0.x + acc[i][1] * a0.y + acc[i][2] * a0.z + acc[i][3] * a0.w;
        float pd0 = acc[i][0] * d0.x + acc[i][1] * d0.y + acc[i][2] * d0.z + acc[i][3] * d0.w;
        float ps1 = acc[i][4] * a1.x + acc[i][5] * a1.y + acc[i][6] * a1.z + acc[i][7] * a1.w;
        float pd1 = acc[i][4] * d1.x + acc[i][5] * d1.y + acc[i][6] * d1.z + acc[i][7] * d1.w;
#pragma unroll
        for (int off = 1; off < 16; off <<= 1) {
            ps0 += __shfl_xor_sync(0xffffffffu, ps0, off, 16);
            pd0 += __shfl_xor_sync(0xffffffffu, pd0, off, 16);
            ps1 += __shfl_xor_sync(0xffffffffu, ps1, off, 16);
            pd1 += __shfl_xor_sync(0xffffffffu, pd1, off, 16);
        }
        if (cg == 0 && valid) {
            *(float2*)&g_ss[2 * n] = make_float2(ps0, ps1);
            *(float2*)&g_sd[2 * n] = make_float2(pd0, pd1);
        }
    }
}

// ---------------- GAT aggregation over CSR: softmax + mean + bias + relu -----
// __expf (MUFU.EX2) instead of software expf: ~17 fewer instrs per edge-exp.
__global__ void k_gat_agg(const float* __restrict__ b, float* __restrict__ out) {
    int gt = blockIdx.x * blockDim.x + threadIdx.x;
    int n = gt >> 4;
    if (n >= N_NODES) return;
    int t = threadIdx.x & 15;
    unsigned hm = 0xFFFFu << (threadIdx.x & 16);
    float2 sdv = *(const float2*)&g_sd[2 * n];
    float2 ssn = *(const float2*)&g_ss[2 * n];
    float selfex0 = __expf(leaky(ssn.x + sdv.x));
    float selfex1 = __expf(leaky(ssn.y + sdv.y));
    uint4 u = *(const uint4*)&g_h2x[(size_t)n * 64 + t * 4];
    float2 f0 = __half22float2(*(__half2*)&u.x);
    float2 f1 = __half22float2(*(__half2*)&u.y);
    float2 f2 = __half22float2(*(__half2*)&u.z);
    float2 f3 = __half22float2(*(__half2*)&u.w);
    float num0[4] = { selfex0 * f0.x, selfex0 * f1.x, selfex0 * f2.x, selfex0 * f3.x };
    float num1[4] = { selfex1 * f0.y, selfex1 * f1.y, selfex1 * f2.y, selfex1 * f3.y };
    float den0 = 0.f, den1 = 0.f;      // edge part; self added post-reduce
    int beg = g_off[n];
    int end = beg + g_cnt[n];
    for (int j = beg; j < end; j += 16) {
        int e = j + t;
        int s = 0; float ex0 = 0.f, ex1 = 0.f;
        if (e < end) {
            s = __ldg(&g_epack[e]).x;
            float2 ssv = *(const float2*)&g_ss[2 * s];
            ex0 = __expf(leaky(ssv.x + sdv.x));
            ex1 = __expf(leaky(ssv.y + sdv.y));
        }
        den0 += ex0; den1 += ex1;
        int cnt = min(16, end - j);
        for (int k = 0; k < cnt; k++) {
            int sk   = __shfl_sync(hm, s, k, 16);
            float c0 = __shfl_sync(hm, ex0, k, 16);
            float c1 = __shfl_sync(hm, ex1, k, 16);
            uint4 uu = *(const uint4*)&g_h2x[(size_t)sk * 64 + t * 4];
            float2 e0 = __half22float2(*(__half2*)&uu.x);
            float2 e1 = __half22float2(*(__half2*)&uu.y);
            float2 e2 = __half22float2(*(__half2*)&uu.z);
            float2 e3 = __half22float2(*(__half2*)&uu.w);
            num0[0] += c0 * e0.x; num1[0] += c1 * e0.y;
            num0[1] += c0 * e1.x; num1[1] += c1 * e1.y;
            num0[2] += c0 * e2.x; num1[2] += c1 * e2.y;
            num0[3] += c0 * e3.x; num1[3] += c1 * e3.y;
        }
    }
#pragma unroll
    for (int off = 1; off < 16; off <<= 1) {
        den0 += __shfl_xor_sync(hm, den0, off, 16);
        den1 += __shfl_xor_sync(hm, den1, off, 16);
    }
    den0 += selfex0;   // every lane computed identical self terms
    den1 += selfex1;
    float r0 = 0.5f / fmaxf(den0, 1e-16f);
    float r1 = 0.5f / fmaxf(den1, 1e-16f);
    float4 bv = __ldg((const float4*)&b[t * 4]);
    *(float4*)&out[(size_t)n * 64 + t * 4] =
        make_float4(fmaxf(num0[0] * r0 + num1[0] * r1 + bv.x, 0.f),
                    fmaxf(num0[1] * r0 + num1[1] * r1 + bv.y, 0.f),
                    fmaxf(num0[2] * r0 + num1[2] * r1 + bv.z, 0.f),
                    fmaxf(num0[3] * r0 + num1[3] * r1 + bv.w, 0.f));
}

// ---------------- launch -----------------------------------------------------
static cudaStream_t g_s2 = 0;
static cudaEvent_t  g_evF = 0, g_evJ = 0;

extern "C" void kernel_launch(void* const* d_in, const int* in_sizes, int n_in,
                              void* d_out, int out_size) {
    const float* x       = (const float*)d_in[0];
    const int*   ei      = (const int*)d_in[1];
    const float* ew      = (const float*)d_in[2];
    const float* gcn_w   = (const float*)d_in[3];
    const float* gcn_b   = (const float*)d_in[4];
    const float* gat_w   = (const float*)d_in[5];
    const float* att_src = (const float*)d_in[6];
    const float* att_dst = (const float*)d_in[7];
    const float* gat_b   = (const float*)d_in[8];
    float* out = (float*)d_out;
    const int* src = ei;
    const int* dst = ei + E_EDGES;

    if (!g_s2) {   // first call is the (uncaptured) correctness run
        cudaStreamCreateWithFlags(&g_s2, cudaStreamNonBlocking);
        cudaEventCreateWithFlags(&g_evF, cudaEventDisableTiming);
        cudaEventCreateWithFlags(&g_evJ, cudaEventDisableTiming);
    }

    const int B = 256;
    // fork: degree + CSR build on stream 2, overlapped with gemm1
    cudaEventRecord(g_evF, 0);
    cudaStreamWaitEvent(g_s2, g_evF, 0);
    k_deg_init<<<(N_NODES + B - 1) / B, B, 0, g_s2>>>();
    k_deg_edges<<<(E_EDGES + B - 1) / B, B, 0, g_s2>>>(dst, ew);
    k_scan1<<<NB_SCAN, 1024, 0, g_s2>>>();
    k_scan2<<<1, 32, 0, g_s2>>>();
    k_scan3<<<(N_NODES + B - 1) / B, B, 0, g_s2>>>();
    k_scatter<<<(E_EDGES + B - 1) / B, B, 0, g_s2>>>(src, dst, ew);
    cudaEventRecord(g_evJ, g_s2);

    // main stream: gemm1 (depends only on x, W)
    k_gemm1<<<(N_NODES + 127) / 128, B>>>(x, gcn_w);

    // join, then the dependent chain
    cudaStreamWaitEvent(0, g_evJ, 0);
    k_gcn_agg<<<(N_NODES * 16 + B - 1) / B, B>>>();
    k_gemm2<<<(N_NODES + 63) / 64, B>>>(gat_w, att_src, att_dst, gcn_b);
    k_gat_agg<<<(N_NODES * 16 + B - 1) / B, B>>>(gat_b, out);
}